// round 2
// baseline (speedup 1.0000x reference)
#include <cuda_runtime.h>

// PolyMinLayer: minimize p(x), p of degree 6 (7 coeffs, lowest-first),
// via damped Newton (GD fallback) matching the JAX reference:
//   while (g2 > 1e-12 && it < 100):
//     g = p'(x); h = p''(x)
//     step = (h > 0) ? g/h : 0.1*g
//     x -= step; g2 = p'(x)^2; it++
// Single scalar -> one thread. Runtime is pure launch overhead + serial
// dependency chain.

#define GRAD_SQ_TOL 1e-12f
#define MAX_ITER 100

__device__ __forceinline__ float horner7(const float* a, int m, float x) {
    // Evaluate sum_{i<m} a[i]*x^i, m <= 7, lowest-degree-first, via Horner.
    float r = 0.0f;
    #pragma unroll
    for (int i = 6; i >= 0; --i) {
        if (i < m) r = fmaf(r, x, a[i]);
    }
    return r;
}

__global__ void polymin_kernel(const float* __restrict__ poly,
                               const float* __restrict__ x_init,
                               float* __restrict__ out,
                               int ncoef) {
    if (threadIdx.x != 0 || blockIdx.x != 0) return;

    // Load coefficients (degree <= 6 expected; handle up to 8 defensively).
    float c[8];
    #pragma unroll
    for (int i = 0; i < 8; ++i) c[i] = (i < ncoef) ? poly[i] : 0.0f;
    int n = ncoef;

    // d1 = p' (n-1 coeffs), d2 = p'' (n-2 coeffs), lowest-first.
    float d1[7], d2[7];
    int n1 = n - 1;
    #pragma unroll
    for (int i = 0; i < 7; ++i) d1[i] = (i < n1) ? c[i + 1] * (float)(i + 1) : 0.0f;
    int n2 = n1 - 1;
    #pragma unroll
    for (int i = 0; i < 7; ++i) d2[i] = (i < n2) ? d1[i + 1] * (float)(i + 1) : 0.0f;

    float x = x_init[0];
    float g2 = __int_as_float(0x7f800000);  // +inf
    int it = 0;

    while (g2 > GRAD_SQ_TOL && it < MAX_ITER) {
        float g = horner7(d1, n1, x);
        float h = horner7(d2, n2, x);
        float step = (h > 0.0f) ? (g / h) : (0.1f * g);
        x = x - step;
        float gn = horner7(d1, n1, x);
        g2 = gn * gn;
        ++it;
    }

    out[0] = x;
}

extern "C" void kernel_launch(void* const* d_in, const int* in_sizes, int n_in,
                              void* d_out, int out_size) {
    const float* poly = (const float*)d_in[0];
    const float* x_init = (const float*)d_in[1];
    float* out = (float*)d_out;
    int ncoef = in_sizes[0];
    polymin_kernel<<<1, 32>>>(poly, x_init, out, ncoef);
}

// round 3
// speedup vs baseline: 1.0048x; 1.0048x over previous
#include <cuda_runtime.h>

// PolyMinLayer: minimize degree-6 p(x) via damped Newton (GD fallback),
// matching the JAX reference loop:
//   g2=inf; it=0
//   while (g2 > 1e-12 && it < 100):
//     g = p'(x); h = p''(x)
//     step = (h>0) ? g/h : 0.1*g
//     x -= step; g2 = p'(x)^2; it++
//
// Latency-optimized single-thread kernel:
//  - g carried across iterations (top-of-body g == previous g_new, bit-exact)
//  - __fdividef (RCP+MUL) instead of IEEE divide
//  - fully-flattened Horner chains specialized for 7 coefficients
//  - 2x unroll so setp+branch cost is paid every other iteration
//    (at most one extra benign iteration near convergence; it-cap exact)

#define GRAD_SQ_TOL 1e-12f
#define MAX_ITER 100

__device__ __forceinline__ float eval_d1(float x, float a0, float a1, float a2,
                                         float a3, float a4, float a5) {
    // p'(x), 6 coeffs lowest-first
    return fmaf(fmaf(fmaf(fmaf(fmaf(a5, x, a4), x, a3), x, a2), x, a1), x, a0);
}

__device__ __forceinline__ float eval_d2(float x, float b0, float b1, float b2,
                                         float b3, float b4) {
    // p''(x), 5 coeffs lowest-first
    return fmaf(fmaf(fmaf(fmaf(b4, x, b3), x, b2), x, b1), x, b0);
}

__global__ void polymin7_kernel(const float* __restrict__ poly,
                                const float* __restrict__ x_init,
                                float* __restrict__ out) {
    if (threadIdx.x != 0 || blockIdx.x != 0) return;

    const float c1 = poly[1], c2 = poly[2], c3 = poly[3];
    const float c4 = poly[4], c5 = poly[5], c6 = poly[6];

    // d1 = p' coefficients (lowest-first)
    const float a0 = c1;
    const float a1 = 2.0f * c2;
    const float a2 = 3.0f * c3;
    const float a3 = 4.0f * c4;
    const float a4 = 5.0f * c5;
    const float a5 = 6.0f * c6;
    // d2 = p'' coefficients
    const float b0 = 2.0f * c2;
    const float b1 = 6.0f * c3;
    const float b2 = 12.0f * c4;
    const float b3 = 20.0f * c5;
    const float b4 = 30.0f * c6;

    float x = x_init[0];
    // Reference enters the body at least once (g2 starts at inf).
    // Carried g: top-of-body g equals previous iteration's g_new.
    float g = eval_d1(x, a0, a1, a2, a3, a4, a5);
    float g2 = __int_as_float(0x7f800000);  // +inf -> first pair always runs

    #pragma unroll 1
    for (int it = 0; it < MAX_ITER; it += 2) {
        if (g2 <= GRAD_SQ_TOL) break;

        // --- iteration A ---
        {
            float h = eval_d2(x, b0, b1, b2, b3, b4);
            float newton = __fdividef(g, h);
            float step = (h > 0.0f) ? newton : 0.1f * g;
            x = x - step;
            g = eval_d1(x, a0, a1, a2, a3, a4, a5);
        }
        // --- iteration B (may be one benign extra step past convergence) ---
        {
            float h = eval_d2(x, b0, b1, b2, b3, b4);
            float newton = __fdividef(g, h);
            float step = (h > 0.0f) ? newton : 0.1f * g;
            x = x - step;
            g = eval_d1(x, a0, a1, a2, a3, a4, a5);
        }
        g2 = g * g;
    }

    out[0] = x;
}

extern "C" void kernel_launch(void* const* d_in, const int* in_sizes, int n_in,
                              void* d_out, int out_size) {
    const float* poly = (const float*)d_in[0];
    const float* x_init = (const float*)d_in[1];
    float* out = (float*)d_out;
    // This problem instance always has 7 coefficients (degree 6).
    polymin7_kernel<<<1, 32>>>(poly, x_init, out);
}

// round 4
// speedup vs baseline: 1.0667x; 1.0615x over previous
#include <cuda_runtime.h>

// PolyMinLayer: minimize degree-6 p(x) via damped Newton (GD fallback),
// matching the JAX reference loop:
//   g2=inf; it=0
//   while (g2 > 1e-12 && it < 100):
//     g = p'(x); h = p''(x)
//     step = (h>0) ? g/h : 0.1*g
//     x -= step; g2 = p'(x)^2; it++
//
// Latency-optimized single-thread kernel:
//  - g carried across iterations (top-of-body g == previous g_new)
//  - Estrin evaluation: h ready in 12 cyc (vs 16 Horner), g in 12 (vs 20)
//  - __fdividef (RCP+MUL) instead of IEEE divide
//  - convergence check every 4 iterations (branch cost amortized; extra
//    post-convergence Newton steps are sub-ulp contractions; 100%4==0 so
//    the iteration cap is exact)

#define GRAD_SQ_TOL 1e-12f
#define MAX_ITER 100

struct GH { float g, h; };

// Evaluate p' (6 coeffs a0..a5) and p'' (5 coeffs b0..b4) at x via Estrin.
// Critical path: x2@4 -> h@12, g@12.
__device__ __forceinline__ GH eval_gh(float x,
                                      float a0, float a1, float a2,
                                      float a3, float a4, float a5,
                                      float b0, float b1, float b2,
                                      float b3, float b4) {
    float x2 = x * x;                  // @4
    // h = (b0 + b1 x) + x2*(b2 + b3 x + b4 x2)
    float r0 = fmaf(b1, x, b0);        // @4
    float r1 = fmaf(b3, x, b2);        // @4
    float r2 = fmaf(b4, x2, r1);       // @8
    float h  = fmaf(r2, x2, r0);       // @12
    // g = (a0 + a1 x + a2 x2) + x3*(a3 + a4 x + a5 x2)
    float q0 = fmaf(a1, x, a0);        // @4
    float q1 = fmaf(a2, x2, q0);       // @8
    float q2 = fmaf(a4, x, a3);        // @4
    float q3 = fmaf(a5, x2, q2);       // @8
    float x3 = x2 * x;                 // @8
    float g  = fmaf(q3, x3, q1);       // @12
    GH out; out.g = g; out.h = h;
    return out;
}

__global__ void polymin7_kernel(const float* __restrict__ poly,
                                const float* __restrict__ x_init,
                                float* __restrict__ out) {
    if (threadIdx.x != 0 || blockIdx.x != 0) return;

    const float c1 = poly[1], c2 = poly[2], c3 = poly[3];
    const float c4 = poly[4], c5 = poly[5], c6 = poly[6];

    // d1 = p' coefficients (lowest-first)
    const float a0 = c1;
    const float a1 = 2.0f * c2;
    const float a2 = 3.0f * c3;
    const float a3 = 4.0f * c4;
    const float a4 = 5.0f * c5;
    const float a5 = 6.0f * c6;
    // d2 = p'' coefficients
    const float b0 = 2.0f * c2;
    const float b1 = 6.0f * c3;
    const float b2 = 12.0f * c4;
    const float b3 = 20.0f * c5;
    const float b4 = 30.0f * c6;

    float x = x_init[0];
    GH s = eval_gh(x, a0, a1, a2, a3, a4, a5, b0, b1, b2, b3, b4);
    float g = s.g;
    float g2 = __int_as_float(0x7f800000);  // +inf -> first group always runs

    #pragma unroll 1
    for (int it = 0; it < MAX_ITER; it += 4) {
        if (g2 <= GRAD_SQ_TOL) break;

        #pragma unroll
        for (int k = 0; k < 4; ++k) {
            // h at current x (g already carried from previous eval)
            GH cur = eval_gh(x, a0, a1, a2, a3, a4, a5, b0, b1, b2, b3, b4);
            float h = cur.h;
            float newton = __fdividef(g, h);
            float step = (h > 0.0f) ? newton : 0.1f * g;
            x = x - step;
            GH nxt = eval_gh(x, a0, a1, a2, a3, a4, a5, b0, b1, b2, b3, b4);
            g = nxt.g;
        }
        g2 = g * g;
    }

    out[0] = x;
}

extern "C" void kernel_launch(void* const* d_in, const int* in_sizes, int n_in,
                              void* d_out, int out_size) {
    const float* poly = (const float*)d_in[0];
    const float* x_init = (const float*)d_in[1];
    float* out = (float*)d_out;
    polymin7_kernel<<<1, 32>>>(poly, x_init, out);
}